// round 13
// baseline (speedup 1.0000x reference)
#include <cuda_runtime.h>
#include <cuda_bf16.h>
#include <math.h>
#include <cstdint>

// Problem constants
#define BB 32
#define HH 128
#define WW 128
#define CC 64
#define MY 16
#define NKX 32   // 16 positive kx + 16 negative kx (112..127)

// ---------------------------------------------------------------------------
// Scratch (static device globals — no allocations allowed)
// ---------------------------------------------------------------------------
__device__ __align__(16) __nv_bfloat16 g_P1b[BB * MY * 256 * CC];   // [b][ky][h*2+p][c]
__device__ __align__(16) __nv_bfloat16 g_X2 [NKX * MY * BB * 128];  // [kxi][ky][b][(c,q)]
__device__ __align__(16) __nv_bfloat16 g_Y2 [BB * MY * 64 * CC];    // [b][ky][(kxi,q)][c]
__device__ __align__(16) __nv_bfloat16 g_Z2 [BB * 32 * HH * CC];    // [b][p*16+ky][h][c]
__device__ __align__(16) __nv_bfloat16 g_G2 [64 * 256];             // [kxi*2+p][h*2+q]
__device__ __align__(16) __nv_bfloat16 g_Hinv[256 * 64];            // [(h,p)][(kxi,q)]
__device__ __align__(16) __nv_bfloat16 g_T  [WW * 32];              // [w][j] inverse-W DFT
__device__ __align__(16) __nv_bfloat16 g_Bk [CC * 128];             // [c][k]: K_hi|K_lo

// ---------------------------------------------------------------------------
// helpers
// ---------------------------------------------------------------------------
__device__ __forceinline__ uint32_t smem_u32(const void* p) {
    uint32_t a;
    asm("{ .reg .u64 t; cvta.to.shared.u64 t, %1; cvt.u32.u64 %0, t; }" : "=r"(a) : "l"(p));
    return a;
}
__device__ __forceinline__ void gdc_wait()   { asm volatile("griddepcontrol.wait;" ::: "memory"); }
__device__ __forceinline__ void gdc_launch() { asm volatile("griddepcontrol.launch_dependents;" ::: "memory"); }
__device__ __forceinline__ float tanh_approx(float u) {
    float th;
    asm("tanh.approx.f32 %0, %1;" : "=f"(th) : "f"(u));
    return th;
}

#define LDSM4(r0, r1, r2, r3, addr) \
    asm volatile("ldmatrix.sync.aligned.m8n8.x4.shared.b16 {%0,%1,%2,%3}, [%4];" \
        : "=r"(r0), "=r"(r1), "=r"(r2), "=r"(r3) : "r"(addr))
#define LDSM4T(r0, r1, r2, r3, addr) \
    asm volatile("ldmatrix.sync.aligned.m8n8.x4.trans.shared.b16 {%0,%1,%2,%3}, [%4];" \
        : "=r"(r0), "=r"(r1), "=r"(r2), "=r"(r3) : "r"(addr))

#define MMA16816(d, a0, a1, a2, a3, b0, b1) \
    asm volatile("mma.sync.aligned.m16n8k16.row.col.f32.bf16.bf16.f32 " \
        "{%0,%1,%2,%3}, {%4,%5,%6,%7}, {%8,%9}, {%0,%1,%2,%3};" \
        : "+f"((d)[0]), "+f"((d)[1]), "+f"((d)[2]), "+f"((d)[3]) \
        : "r"(a0), "r"(a1), "r"(a2), "r"(a3), "r"(b0), "r"(b1))

__device__ __forceinline__ uint32_t pack2(__nv_bfloat16 a, __nv_bfloat16 b) {
    return (uint32_t)__bfloat16_as_ushort(a) | ((uint32_t)__bfloat16_as_ushort(b) << 16);
}
__device__ __forceinline__ uint32_t pack2f(float a, float b) {
    return pack2(__float2bfloat16_rn(a), __float2bfloat16_rn(b));
}
__device__ __forceinline__ float bflo(uint32_t u) {
    return __bfloat162float(__ushort_as_bfloat16((unsigned short)(u & 0xFFFF)));
}
__device__ __forceinline__ float bfhi(uint32_t u) {
    return __bfloat162float(__ushort_as_bfloat16((unsigned short)(u >> 16)));
}

// ---------------------------------------------------------------------------
// K1 (mma): blocks [0,2048): per (b, 2h): P1[32,(ky,p) x 64 c] = F2 @ x
//           blocks [2048,2056): generate G2 / Hinv / T / Bk tables
// F2 built from a 128-entry sincos LUT (128 sincos per CTA, not 4096).
// ---------------------------------------------------------------------------
#define K1_SA 136
#define K1_SX 72
#define K1_SMEM_A 0
#define K1_SMEM_X (32 * K1_SA * 2)                       // 8704
#define K1_SMEM_LUT (K1_SMEM_X + 2 * 128 * K1_SX * 2)    // 45568
#define K1_SMEM_TOTAL (K1_SMEM_LUT + 128 * 8)            // 46592

__global__ __launch_bounds__(256) void k1_mma(const float* __restrict__ x,
                                              const float* __restrict__ dk)
{
    extern __shared__ char sm[];
    const int t = threadIdx.x;

    if (blockIdx.x >= 2048) {
        // ---- table generation ----
        const int gid = (blockIdx.x - 2048) * 256 + t;
        const int gs  = 8 * 256;
        for (int i = gid; i < 64 * 256; i += gs) {           // G2
            int m = i >> 8, k = i & 255;
            int kxi = m >> 1, p = m & 1;
            int h = k >> 1, q = k & 1;
            int kx = (kxi < 16) ? kxi : (96 + kxi);
            float s, c;
            sincospif((float)(kx * h) * (1.0f / 64.0f), &s, &c);
            float v = (p == 0) ? (q == 0 ? c : s) : (q == 0 ? -s : c);
            g_G2[i] = __float2bfloat16_rn(v);
        }
        for (int i = gid; i < 256 * 64; i += gs) {           // Hinv
            int m = i >> 6, kq = i & 63;
            int h = m >> 1, p = m & 1;
            int kxi = kq >> 1, q = kq & 1;
            int kx = (kxi < 16) ? kxi : (96 + kxi);
            float s, c;
            sincospif((float)(kx * h) * (1.0f / 64.0f), &s, &c);
            float v = (p == 0) ? (q == 0 ? c : -s) : (q == 0 ? s : c);
            g_Hinv[i] = __float2bfloat16_rn(v * (1.0f / 128.0f));
        }
        for (int i = gid; i < WW * 32; i += gs) {            // T
            int w = i >> 5, j = i & 31, ky = j & 15;
            float s, c;
            sincospif((float)(ky * w) * (1.0f / 64.0f), &s, &c);
            float sc = (ky == 0) ? (1.0f / 128.0f) : (2.0f / 128.0f);
            g_T[i] = __float2bfloat16_rn((j < 16) ? c * sc : -s * sc);
        }
        for (int i = gid; i < CC * 128; i += gs) {           // Bk
            int c = i >> 7, k = i & 127;
            int kk = k & 63;
            float v = dk[kk * 64 + c];
            __nv_bfloat16 hi = __float2bfloat16_rn(v);
            g_Bk[i] = (k < 64) ? hi : __float2bfloat16_rn(v - __bfloat162float(hi));
        }
        gdc_launch();
        return;
    }

    const uint32_t sbase = smem_u32(sm);
    const int b    = blockIdx.x >> 6;
    const int hg   = blockIdx.x & 63;
    const int warp = t >> 5;
    const int lane = t & 31;
    float2* lut = (float2*)(sm + K1_SMEM_LUT);

    // LUT: (cos, sin)(2*pi*i/128)
    if (t < 128) {
        float s, c;
        sincospif((float)t * (1.0f / 64.0f), &s, &c);
        lut[t] = make_float2(c, s);
    }
    // x fill (independent of LUT)
    {
        const float4* xin = (const float4*)(x + ((size_t)(b * HH + hg * 2)) * WW * CC);
        for (int i = t; i < 2 * 128 * 16; i += 256) {
            float4 v = xin[i];
            int hl = i >> 11, w = (i >> 4) & 127, c4 = i & 15;
            uint32_t u0 = pack2f(v.x, v.y);
            uint32_t u1 = pack2f(v.z, v.w);
            *(uint2*)(sm + K1_SMEM_X + ((hl * 128 + w) * K1_SX + c4 * 4) * 2) = make_uint2(u0, u1);
        }
    }
    __syncthreads();
    // F2 fill from LUT
    {
        const int m = t >> 3;
        const int ky = m >> 1, p = m & 1;
        const int w0 = (t & 7) * 16;
        #pragma unroll
        for (int j = 0; j < 16; j += 2) {
            float2 e0 = lut[(ky * (w0 + j)) & 127];
            float2 e1 = lut[(ky * (w0 + j + 1)) & 127];
            uint32_t v = (p == 0) ? pack2f(e0.x, e1.x) : pack2f(-e0.y, -e1.y);
            *(uint32_t*)(sm + K1_SMEM_A + (m * K1_SA + w0 + j) * 2) = v;
        }
    }
    __syncthreads();

    const int hl = warp >> 2, nq = warp & 3;
    const uint32_t Ab = sbase + K1_SMEM_A;
    const uint32_t Xb = sbase + K1_SMEM_X + hl * 128 * K1_SX * 2;

    float acc[2][2][4];
    #pragma unroll
    for (int mt = 0; mt < 2; mt++)
        #pragma unroll
        for (int nt = 0; nt < 2; nt++)
            #pragma unroll
            for (int q = 0; q < 4; q++) acc[mt][nt][q] = 0.f;

    const int arow = lane & 15;
    const int acol = (lane >> 4) * 8;
    const int brow = (lane & 7) + ((lane >> 3) & 1) * 8;
    const int bcol = (lane >> 4) * 8;

    #pragma unroll
    for (int ks = 0; ks < 8; ks++) {
        uint32_t a[2][4];
        #pragma unroll
        for (int mt = 0; mt < 2; mt++) {
            uint32_t addr = Ab + (uint32_t)((mt * 16 + arow) * K1_SA + ks * 16 + acol) * 2;
            LDSM4(a[mt][0], a[mt][1], a[mt][2], a[mt][3], addr);
        }
        uint32_t b0, b1, b2, b3;
        uint32_t addr = Xb + (uint32_t)((ks * 16 + brow) * K1_SX + nq * 16 + bcol) * 2;
        LDSM4T(b0, b1, b2, b3, addr);
        #pragma unroll
        for (int mt = 0; mt < 2; mt++) {
            MMA16816(acc[mt][0], a[mt][0], a[mt][1], a[mt][2], a[mt][3], b0, b1);
            MMA16816(acc[mt][1], a[mt][0], a[mt][1], a[mt][2], a[mt][3], b2, b3);
        }
    }

    __syncthreads();
    __nv_bfloat16* stg = (__nv_bfloat16*)(sm + K1_SMEM_X);
    #pragma unroll
    for (int mt = 0; mt < 2; mt++)
        #pragma unroll
        for (int nt = 0; nt < 2; nt++)
            #pragma unroll
            for (int half = 0; half < 2; half++) {
                int m = mt * 16 + (lane >> 2) + half * 8;
                int ky = m >> 1, p = m & 1;
                int c = nq * 16 + nt * 8 + 2 * (lane & 3);
                int sr = ky * 4 + hl * 2 + p;
                *(uint32_t*)(stg + sr * 72 + c) =
                    pack2f(acc[mt][nt][half * 2], acc[mt][nt][half * 2 + 1]);
            }
    __syncthreads();
    {
        int sr = t >> 2, seg = t & 3;
        int ky = sr >> 2, hl2 = (sr >> 1) & 1, p = sr & 1;
        size_t row = (((size_t)(b * 16 + ky)) * 256 + (hg * 2 + hl2) * 2 + p) * 64 + seg * 16;
        const uint4* src = (const uint4*)(stg + sr * 72 + seg * 16);
        uint4* dst = (uint4*)(g_P1b + row);
        dst[0] = src[0]; dst[1] = src[1];
    }
    gdc_launch();
}

// ---------------------------------------------------------------------------
// K2 (mma): per (b,ky,ch): X[64 m=(kxi,p), 32 c] = G2[64x256] @ P1b[256, c-half]
// ---------------------------------------------------------------------------
#define K2_SA 264
#define K2_SB 40
#define K2_SMEM_A 0
#define K2_SMEM_B (64 * K2_SA * 2)                       // 33792
#define K2_SMEM_TOTAL (K2_SMEM_B + 256 * K2_SB * 2)      // 54272

__global__ __launch_bounds__(256) void k2_mma()
{
    extern __shared__ char sm[];
    const uint32_t sbase = smem_u32(sm);
    const int bky = blockIdx.x >> 1;
    const int b   = bky >> 4;
    const int ky  = bky & 15;
    const int ch  = blockIdx.x & 1;     // c-half
    const int t    = threadIdx.x;
    const int warp = t >> 5;
    const int lane = t & 31;

    gdc_wait();
    {
        const uint4* src = (const uint4*)g_G2;
        #pragma unroll
        for (int i = t; i < 64 * 32; i += 256) {
            int m = i >> 5, c8 = i & 31;
            *(uint4*)(sm + K2_SMEM_A + (m * K2_SA + c8 * 8) * 2) = src[i];
        }
    }
    {
        const __nv_bfloat16* base = g_P1b + ((size_t)(b * 16 + ky)) * 256 * 64 + ch * 32;
        #pragma unroll
        for (int i = t; i < 256 * 4; i += 256) {
            int r = i >> 2, s4 = i & 3;
            *(uint4*)(sm + K2_SMEM_B + (r * K2_SB + s4 * 8) * 2) =
                *(const uint4*)(base + (size_t)r * 64 + s4 * 8);
        }
    }
    __syncthreads();

    const int mi = warp >> 1, nh = warp & 1;
    float acc[2][4];
    #pragma unroll
    for (int nt = 0; nt < 2; nt++)
        #pragma unroll
        for (int q = 0; q < 4; q++) acc[nt][q] = 0.f;

    const int arow = lane & 15;
    const int acol = (lane >> 4) * 8;
    const int brow = (lane & 7) + ((lane >> 3) & 1) * 8;
    const int bcol = (lane >> 4) * 8;

    #pragma unroll
    for (int ks = 0; ks < 16; ks++) {
        uint32_t a0, a1, a2, a3;
        uint32_t aaddr = sbase + K2_SMEM_A + (uint32_t)((mi * 16 + arow) * K2_SA + ks * 16 + acol) * 2;
        LDSM4(a0, a1, a2, a3, aaddr);
        uint32_t b0, b1, b2, b3;
        uint32_t baddr = sbase + K2_SMEM_B
            + (uint32_t)((ks * 16 + brow) * K2_SB + nh * 16 + bcol) * 2;
        LDSM4T(b0, b1, b2, b3, baddr);
        MMA16816(acc[0], a0, a1, a2, a3, b0, b1);
        MMA16816(acc[1], a0, a1, a2, a3, b2, b3);
    }

    __syncthreads();
    __nv_bfloat16* stg = (__nv_bfloat16*)sm;   // [64 m][40]
    #pragma unroll
    for (int nt = 0; nt < 2; nt++)
        #pragma unroll
        for (int half = 0; half < 2; half++) {
            int m = mi * 16 + (lane >> 2) + half * 8;
            int c = nh * 16 + nt * 8 + 2 * (lane & 3);
            *(uint32_t*)(stg + m * 40 + c) = pack2f(acc[nt][half * 2], acc[nt][half * 2 + 1]);
        }
    __syncthreads();
    {
        int kxi = t >> 3, seg = t & 7;
        uint32_t vals[4];
        #pragma unroll
        for (int u = 0; u < 4; u++) {
            int cl = seg * 4 + u;
            vals[u] = pack2(stg[(2 * kxi) * 40 + cl], stg[(2 * kxi + 1) * 40 + cl]);
        }
        uint4* dst = (uint4*)(g_X2 + ((size_t)(kxi * 16 + ky) * 32 + b) * 128 + ch * 64 + seg * 8);
        dst[0] = make_uint4(vals[0], vals[1], vals[2], vals[3]);
    }
    gdc_launch();
}

// ---------------------------------------------------------------------------
// K3 (mma): per (kxi,ky,oh): Y[32 b, 64 (o-half,p)] = X2[32x128] @ W2[128 x half]
// ---------------------------------------------------------------------------
__global__ __launch_bounds__(256) void k3_mma(const float* __restrict__ w1r,
                                              const float* __restrict__ w1i,
                                              const float* __restrict__ w2r,
                                              const float* __restrict__ w2i)
{
    __shared__ __nv_bfloat16 sA[32 * 136];
    __shared__ __nv_bfloat16 sB[128 * 72];
    const int kq   = blockIdx.x >> 1;
    const int oh   = blockIdx.x & 1;
    const int o0   = oh * 32;
    const int kxi  = kq >> 4, ky = kq & 15;
    const int t    = threadIdx.x;
    const int warp = t >> 5;
    const int lane = t & 31;

    {
        const float* wr;
        const float* wi;
        if (kxi < 16) { size_t off = (size_t)(kxi * 16 + ky) * 4096; wr = w1r + off; wi = w1i + off; }
        else          { size_t off = (size_t)((kxi - 16) * 16 + ky) * 4096; wr = w2r + off; wi = w2i + off; }
        const int ii   = t >> 2;
        const int part = t & 3;
        const float4* wr4 = (const float4*)(wr + ii * 64 + o0 + part * 8);
        const float4* wi4 = (const float4*)(wi + ii * 64 + o0 + part * 8);
        float4 r0 = wr4[0], r1 = wr4[1];
        float4 i0 = wi4[0], i1 = wi4[1];
        uint4 q0a = make_uint4(pack2f(r0.x, i0.x), pack2f(r0.y, i0.y),
                               pack2f(r0.z, i0.z), pack2f(r0.w, i0.w));
        uint4 q0b = make_uint4(pack2f(r1.x, i1.x), pack2f(r1.y, i1.y),
                               pack2f(r1.z, i1.z), pack2f(r1.w, i1.w));
        uint4 q1a = make_uint4(pack2f(-i0.x, r0.x), pack2f(-i0.y, r0.y),
                               pack2f(-i0.z, r0.z), pack2f(-i0.w, r0.w));
        uint4 q1b = make_uint4(pack2f(-i1.x, r1.x), pack2f(-i1.y, r1.y),
                               pack2f(-i1.z, r1.z), pack2f(-i1.w, r1.w));
        *(uint4*)(sB + (2 * ii) * 72 + part * 16)       = q0a;
        *(uint4*)(sB + (2 * ii) * 72 + part * 16 + 8)   = q0b;
        *(uint4*)(sB + (2 * ii + 1) * 72 + part * 16)     = q1a;
        *(uint4*)(sB + (2 * ii + 1) * 72 + part * 16 + 8) = q1b;
    }
    gdc_wait();
    {
        const uint4* src = (const uint4*)(g_X2 + (size_t)kq * 32 * 128);
        #pragma unroll
        for (int i = t; i < 512; i += 256) {
            int r = i >> 4, c8 = i & 15;
            *(uint4*)(sA + r * 136 + c8 * 8) = src[i];
        }
    }
    __syncthreads();

    const uint32_t sAb = smem_u32(sA);
    const uint32_t sBb = smem_u32(sB);
    const int wm = warp >> 2, wn = warp & 3;
    float acc[2][4];
    #pragma unroll
    for (int nt = 0; nt < 2; nt++)
        #pragma unroll
        for (int q = 0; q < 4; q++) acc[nt][q] = 0.f;

    const int arow = lane & 15;
    const int acol = (lane >> 4) * 8;
    const int bkr  = (lane & 7) + ((lane >> 3) & 1) * 8;
    const int bcol = (lane >> 4) * 8;

    #pragma unroll
    for (int ks = 0; ks < 8; ks++) {
        uint32_t a0, a1, a2, a3;
        LDSM4(a0, a1, a2, a3,
              sAb + (uint32_t)((wm * 16 + arow) * 136 + ks * 16 + acol) * 2);
        uint32_t b0, b1, b2, b3;
        LDSM4T(b0, b1, b2, b3,
               sBb + (uint32_t)((ks * 16 + bkr) * 72 + wn * 16 + bcol) * 2);
        MMA16816(acc[0], a0, a1, a2, a3, b0, b1);
        MMA16816(acc[1], a0, a1, a2, a3, b2, b3);
    }

    __syncthreads();
    __nv_bfloat16* stg = sB;
    #pragma unroll
    for (int nt = 0; nt < 2; nt++)
        #pragma unroll
        for (int half = 0; half < 2; half++) {
            int bi = wm * 16 + (lane >> 2) + half * 8;
            int nl = wn * 16 + nt * 8 + 2 * (lane & 3);
            int ol = nl >> 1;
            stg[bi * 72 + ol]      = __float2bfloat16_rn(acc[nt][half * 2]);
            stg[bi * 72 + 32 + ol] = __float2bfloat16_rn(acc[nt][half * 2 + 1]);
        }
    __syncthreads();
    {
        int bi = t >> 3, seg = t & 7;
        int p = seg >> 2, qq = seg & 3;
        const uint4* src = (const uint4*)(stg + bi * 72 + p * 32 + qq * 8);
        uint4* dst = (uint4*)(g_Y2 + (((size_t)(bi * 16 + ky)) * 64 + kxi * 2 + p) * 64 + o0 + qq * 8);
        dst[0] = src[0];
    }
    gdc_launch();
}

// ---------------------------------------------------------------------------
// K4 (mma): per (b,ky): Z[256 (h,p), 64 c] = Hinv[256x64] @ Y2[64x64]
// ---------------------------------------------------------------------------
__global__ __launch_bounds__(256) void k4_mma()
{
    __shared__ __nv_bfloat16 sA[256 * 72];
    __shared__ __nv_bfloat16 sB[64 * 72];
    const int b    = blockIdx.x >> 4;
    const int ky   = blockIdx.x & 15;
    const int t    = threadIdx.x;
    const int warp = t >> 5;
    const int lane = t & 31;

    {
        const uint4* src = (const uint4*)g_Hinv;
        #pragma unroll
        for (int i = t; i < 256 * 8; i += 256) {
            int r = i >> 3, c8 = i & 7;
            *(uint4*)(sA + r * 72 + c8 * 8) = src[i];
        }
    }
    gdc_wait();
    {
        const uint4* src = (const uint4*)(g_Y2 + ((size_t)b * 16 + ky) * 64 * 64);
        #pragma unroll
        for (int i = t; i < 64 * 8; i += 256) {
            int r = i >> 3, c8 = i & 7;
            *(uint4*)(sB + r * 72 + c8 * 8) = src[i];
        }
    }
    __syncthreads();

    const uint32_t sAb = smem_u32(sA);
    const uint32_t sBb = smem_u32(sB);
    const int wm = warp >> 1, wn = warp & 1;

    float acc[4][4][4];
    #pragma unroll
    for (int mt = 0; mt < 4; mt++)
        #pragma unroll
        for (int g = 0; g < 4; g++)
            #pragma unroll
            for (int q = 0; q < 4; q++) acc[mt][g][q] = 0.f;

    const int arow = lane & 15;
    const int acol = (lane >> 4) * 8;
    const int bkr  = (lane & 7) + ((lane >> 3) & 1) * 8;
    const int bcol = (lane >> 4) * 8;

    #pragma unroll
    for (int ks = 0; ks < 4; ks++) {
        uint32_t a[4][4];
        #pragma unroll
        for (int mt = 0; mt < 4; mt++)
            LDSM4(a[mt][0], a[mt][1], a[mt][2], a[mt][3],
                  sAb + (uint32_t)((wm * 64 + mt * 16 + arow) * 72 + ks * 16 + acol) * 2);
        #pragma unroll
        for (int np = 0; np < 2; np++) {
            uint32_t b0, b1, b2, b3;
            LDSM4T(b0, b1, b2, b3,
                   sBb + (uint32_t)((ks * 16 + bkr) * 72 + wn * 32 + np * 16 + bcol) * 2);
            #pragma unroll
            for (int mt = 0; mt < 4; mt++) {
                MMA16816(acc[mt][np * 2],     a[mt][0], a[mt][1], a[mt][2], a[mt][3], b0, b1);
                MMA16816(acc[mt][np * 2 + 1], a[mt][0], a[mt][1], a[mt][2], a[mt][3], b2, b3);
            }
        }
    }

    #pragma unroll
    for (int mt = 0; mt < 4; mt++)
        #pragma unroll
        for (int g = 0; g < 4; g++)
            #pragma unroll
            for (int half = 0; half < 2; half++) {
                int m = wm * 64 + mt * 16 + (lane >> 2) + half * 8;
                int h = m >> 1, p = m & 1;
                int n = wn * 32 + g * 8 + 2 * (lane & 3);
                size_t addr = (((size_t)b * 32 + p * 16 + ky) * 128 + h) * 64 + n;
                *(uint32_t*)(g_Z2 + addr) = pack2f(acc[mt][g][half * 2], acc[mt][g][half * 2 + 1]);
            }
    gdc_launch();
}

// ---------------------------------------------------------------------------
// K5: mma.sync bf16 GEMM; 2 CTAs per (b,h), 64 w-rows each
// ---------------------------------------------------------------------------
#define SA 168
#define SB 136
#define SZ 72
#define K5_BIAS 0
#define K5_A    256
#define K5_B    (K5_A + 64 * SA * 2)      // 21760
#define K5_ZB   (K5_B + 64 * SB * 2)      // 39168
#define K5_SMEM (K5_ZB + 32 * SZ * 2)     // 43776

__global__ __launch_bounds__(256) void k5_mma(const float* __restrict__ x,
                                              const float* __restrict__ bias,
                                              float* __restrict__ out)
{
    extern __shared__ char smem[];
    const uint32_t sbase = smem_u32(smem);
    const int bh   = blockIdx.x >> 1;
    const int mh   = blockIdx.x & 1;
    const int t    = threadIdx.x;
    const int warp = t >> 5;
    const int lane = t & 31;

    // ---- A fill: x_hi (0..63), x_lo (64..127) ----
    {
        const int w  = t >> 2;
        const int c0 = (t & 3) * 16;
        const float4* xr4 = (const float4*)(x + (size_t)bh * 8192
                                            + (size_t)(mh * 64 + w) * 64 + c0);
        #pragma unroll
        for (int q = 0; q < 4; q++) {
            float4 v = xr4[q];
            __nv_bfloat16 h0 = __float2bfloat16_rn(v.x), h1 = __float2bfloat16_rn(v.y);
            __nv_bfloat16 h2 = __float2bfloat16_rn(v.z), h3 = __float2bfloat16_rn(v.w);
            uint32_t uhA = pack2(h0, h1), uhB = pack2(h2, h3);
            uint32_t ulA = pack2(__float2bfloat16_rn(v.x - __bfloat162float(h0)),
                                 __float2bfloat16_rn(v.y - __bfloat162float(h1)));
            uint32_t ulB = pack2(__float2bfloat16_rn(v.z - __bfloat162float(h2)),
                                 __float2bfloat16_rn(v.w - __bfloat162float(h3)));
            *(uint2*)(smem + K5_A + (w * SA + c0 + q * 4) * 2)      = make_uint2(uhA, uhB);
            *(uint2*)(smem + K5_A + (w * SA + 64 + c0 + q * 4) * 2) = make_uint2(ulA, ulB);
        }
    }
    // ---- A fill: T block (cols 128..159), table ----
    if (t < 64) {
        const uint4* ts = (const uint4*)(g_T + (mh * 64 + t) * 32);
        #pragma unroll
        for (int ch = 0; ch < 4; ch++)
            *(uint4*)(smem + K5_A + (t * SA + 128 + ch * 8) * 2) = ts[ch];
    }
    // ---- B fill: K_hi | K_lo table ----
    {
        const int c = t >> 2;
        const int q4 = t & 3;
        const uint4* src = (const uint4*)(g_Bk + c * 128 + q4 * 32);
        uint4* dst = (uint4*)(smem + K5_B + (c * SB + q4 * 32) * 2);
        dst[0] = src[0]; dst[1] = src[1]; dst[2] = src[2]; dst[3] = src[3];
    }
    if (t < 64) ((float*)(smem + K5_BIAS))[t] = bias[t];

    gdc_wait();
    // ---- Zb fill (depends on k4) ----
    {
        const int b = bh >> 7, h = bh & 127;
        const int j = t >> 3, seg = t & 7;
        const uint4* src = (const uint4*)(g_Z2 + (((size_t)b * 32 + j) * 128 + h) * 64 + seg * 8);
        *(uint4*)(smem + K5_ZB + (j * SZ + seg * 8) * 2) = src[0];
    }
    __syncthreads();

    const int wm = warp >> 1, wn = warp & 1;
    float acc[4][4];
    #pragma unroll
    for (int nt = 0; nt < 4; nt++) {
        acc[nt][0] = 0.f; acc[nt][1] = 0.f; acc[nt][2] = 0.f; acc[nt][3] = 0.f;
    }

    const int arow  = wm * 16 + (lane & 7) + ((lane >> 3) & 1) * 8;
    const int akoff = (lane >> 4) * 8;
    const int brow  = (lane & 7) + (lane >> 4) * 8;
    const int bkoff = ((lane >> 3) & 1) * 8;
    const int zrow  = (lane & 7) + ((lane >> 3) & 1) * 8;
    const int zcol  = (lane >> 4) * 8;

    const int passes[3][2] = { {0, 0}, {0, 64}, {64, 0} };
    #pragma unroll
    for (int p = 0; p < 3; p++) {
        const int kA = passes[p][0], kB = passes[p][1];
        #pragma unroll
        for (int ks = 0; ks < 4; ks++) {
            uint32_t a0, a1, a2, a3;
            uint32_t aaddr = sbase + K5_A + (uint32_t)(arow * SA + kA + ks * 16 + akoff) * 2;
            LDSM4(a0, a1, a2, a3, aaddr);
            #pragma unroll
            for (int nt2 = 0; nt2 < 2; nt2++) {
                uint32_t b0, b1, b2, b3;
                uint32_t baddr = sbase + K5_B
                    + (uint32_t)((wn * 32 + nt2 * 16 + brow) * SB + kB + ks * 16 + bkoff) * 2;
                LDSM4(b0, b1, b2, b3, baddr);
                MMA16816(acc[2 * nt2],     a0, a1, a2, a3, b0, b1);
                MMA16816(acc[2 * nt2 + 1], a0, a1, a2, a3, b2, b3);
            }
        }
    }
    #pragma unroll
    for (int ks = 0; ks < 2; ks++) {
        uint32_t a0, a1, a2, a3;
        uint32_t aaddr = sbase + K5_A + (uint32_t)(arow * SA + 128 + ks * 16 + akoff) * 2;
        LDSM4(a0, a1, a2, a3, aaddr);
        #pragma unroll
        for (int nt2 = 0; nt2 < 2; nt2++) {
            uint32_t b0, b1, b2, b3;
            uint32_t baddr = sbase + K5_ZB
                + (uint32_t)((ks * 16 + zrow) * SZ + wn * 32 + nt2 * 16 + zcol) * 2;
            LDSM4T(b0, b1, b2, b3, baddr);
            MMA16816(acc[2 * nt2],     a0, a1, a2, a3, b0, b1);
            MMA16816(acc[2 * nt2 + 1], a0, a1, a2, a3, b2, b3);
        }
    }

    const int r0 = wm * 16 + (lane >> 2);
    const float* bs = (const float*)(smem + K5_BIAS);
    #pragma unroll
    for (int half = 0; half < 2; half++) {
        const int r = r0 + half * 8;
        float* orow = out + (size_t)bh * 8192 + (size_t)(mh * 64 + r) * 64;
        #pragma unroll
        for (int nt = 0; nt < 4; nt++) {
            const int c = wn * 32 + nt * 8 + 2 * (lane & 3);
            uint32_t hp = *(const uint32_t*)(smem + K5_A + (r * SA + c) * 2);
            uint32_t lp = *(const uint32_t*)(smem + K5_A + (r * SA + 64 + c) * 2);
            float res0 = bflo(hp) + bflo(lp);
            float res1 = bfhi(hp) + bfhi(lp);
            float s0 = acc[nt][half * 2 + 0] + res0 + bs[c];
            float s1 = acc[nt][half * 2 + 1] + res1 + bs[c + 1];
            float u0 = 0.7978845608028654f * (s0 + 0.044715f * s0 * s0 * s0);
            float u1 = 0.7978845608028654f * (s1 + 0.044715f * s1 * s1 * s1);
            float g0 = 0.5f * s0 * (1.0f + tanh_approx(u0));
            float g1 = 0.5f * s1 * (1.0f + tanh_approx(u1));
            *(float2*)(orow + c) = make_float2(g0, g1);
        }
    }
}

// ---------------------------------------------------------------------------
// Launch (PDL-chained)
// ---------------------------------------------------------------------------
extern "C" void kernel_launch(void* const* d_in, const int* in_sizes, int n_in,
                              void* d_out, int out_size)
{
    const float* x   = (const float*)d_in[0];
    const float* w1r = (const float*)d_in[1];
    const float* w1i = (const float*)d_in[2];
    const float* w2r = (const float*)d_in[3];
    const float* w2i = (const float*)d_in[4];
    const float* dk  = (const float*)d_in[5];
    const float* db  = (const float*)d_in[6];
    float* out = (float*)d_out;

    static int configured = 0;
    if (!configured) {
        cudaFuncSetAttribute(k1_mma, cudaFuncAttributeMaxDynamicSharedMemorySize, K1_SMEM_TOTAL);
        cudaFuncSetAttribute(k2_mma, cudaFuncAttributeMaxDynamicSharedMemorySize, K2_SMEM_TOTAL);
        cudaFuncSetAttribute(k5_mma, cudaFuncAttributeMaxDynamicSharedMemorySize, K5_SMEM);
        configured = 1;
    }

    cudaLaunchAttribute at[1];
    at[0].id = cudaLaunchAttributeProgrammaticStreamSerialization;
    at[0].val.programmaticStreamSerializationAllowed = 1;

    k1_mma<<<BB * 64 + 8, 256, K1_SMEM_TOTAL>>>(x, dk);

    {
        cudaLaunchConfig_t cfg = {};
        cfg.gridDim = dim3(BB * MY * 2);
        cfg.blockDim = dim3(256);
        cfg.dynamicSmemBytes = K2_SMEM_TOTAL;
        cfg.stream = 0;
        cfg.attrs = at; cfg.numAttrs = 1;
        cudaLaunchKernelEx(&cfg, k2_mma);
    }
    {
        cudaLaunchConfig_t cfg = {};
        cfg.gridDim = dim3(1024);
        cfg.blockDim = dim3(256);
        cfg.dynamicSmemBytes = 0;
        cfg.stream = 0;
        cfg.attrs = at; cfg.numAttrs = 1;
        cudaLaunchKernelEx(&cfg, k3_mma, w1r, w1i, w2r, w2i);
    }
    {
        cudaLaunchConfig_t cfg = {};
        cfg.gridDim = dim3(BB * MY);
        cfg.blockDim = dim3(256);
        cfg.dynamicSmemBytes = 0;
        cfg.stream = 0;
        cfg.attrs = at; cfg.numAttrs = 1;
        cudaLaunchKernelEx(&cfg, k4_mma);
    }
    {
        cudaLaunchConfig_t cfg = {};
        cfg.gridDim = dim3(BB * HH * 2);
        cfg.blockDim = dim3(256);
        cfg.dynamicSmemBytes = K5_SMEM;
        cfg.stream = 0;
        cfg.attrs = at; cfg.numAttrs = 1;
        cudaLaunchKernelEx(&cfg, k5_mma, x, db, out);
    }
}

// round 15
// speedup vs baseline: 1.1102x; 1.1102x over previous
#include <cuda_runtime.h>
#include <cuda_bf16.h>
#include <math.h>
#include <cstdint>

// Problem constants
#define BB 32
#define HH 128
#define WW 128
#define CC 64
#define MY 16
#define NKX 32   // 16 positive kx + 16 negative kx (112..127)

// ---------------------------------------------------------------------------
// Scratch (static device globals — no allocations allowed)
// ---------------------------------------------------------------------------
__device__ __align__(16) __nv_bfloat16 g_P1b[BB * MY * 256 * CC];   // [b][ky][h*2+p][c]
__device__ __align__(16) __nv_bfloat16 g_X2 [NKX * MY * BB * 128];  // [kxi][ky][b][(c,q)]
__device__ __align__(16) __nv_bfloat16 g_Y2 [BB * MY * 64 * CC];    // [b][ky][(kxi,q)][c]
__device__ __align__(16) __nv_bfloat16 g_Z2 [BB * 32 * HH * CC];    // [b][p*16+ky][h][c]
__device__ __align__(16) __nv_bfloat16 g_G2 [64 * 256];             // [kxi*2+p][h*2+q]
__device__ __align__(16) __nv_bfloat16 g_Hinv[256 * 64];            // [(h,p)][(kxi,q)]
__device__ __align__(16) __nv_bfloat16 g_T  [WW * 32];              // [w][j] inverse-W DFT
__device__ __align__(16) __nv_bfloat16 g_Bk [CC * 128];             // [c][k]: K_hi|K_lo

// ---------------------------------------------------------------------------
// helpers
// ---------------------------------------------------------------------------
__device__ __forceinline__ uint32_t smem_u32(const void* p) {
    uint32_t a;
    asm("{ .reg .u64 t; cvta.to.shared.u64 t, %1; cvt.u32.u64 %0, t; }" : "=r"(a) : "l"(p));
    return a;
}
__device__ __forceinline__ void gdc_wait()   { asm volatile("griddepcontrol.wait;" ::: "memory"); }
__device__ __forceinline__ void gdc_launch() { asm volatile("griddepcontrol.launch_dependents;" ::: "memory"); }
__device__ __forceinline__ float tanh_approx(float u) {
    float th;
    asm("tanh.approx.f32 %0, %1;" : "=f"(th) : "f"(u));
    return th;
}

#define LDSM4(r0, r1, r2, r3, addr) \
    asm volatile("ldmatrix.sync.aligned.m8n8.x4.shared.b16 {%0,%1,%2,%3}, [%4];" \
        : "=r"(r0), "=r"(r1), "=r"(r2), "=r"(r3) : "r"(addr))
#define LDSM4T(r0, r1, r2, r3, addr) \
    asm volatile("ldmatrix.sync.aligned.m8n8.x4.trans.shared.b16 {%0,%1,%2,%3}, [%4];" \
        : "=r"(r0), "=r"(r1), "=r"(r2), "=r"(r3) : "r"(addr))

#define MMA16816(d, a0, a1, a2, a3, b0, b1) \
    asm volatile("mma.sync.aligned.m16n8k16.row.col.f32.bf16.bf16.f32 " \
        "{%0,%1,%2,%3}, {%4,%5,%6,%7}, {%8,%9}, {%0,%1,%2,%3};" \
        : "+f"((d)[0]), "+f"((d)[1]), "+f"((d)[2]), "+f"((d)[3]) \
        : "r"(a0), "r"(a1), "r"(a2), "r"(a3), "r"(b0), "r"(b1))

__device__ __forceinline__ uint32_t pack2(__nv_bfloat16 a, __nv_bfloat16 b) {
    return (uint32_t)__bfloat16_as_ushort(a) | ((uint32_t)__bfloat16_as_ushort(b) << 16);
}
__device__ __forceinline__ uint32_t pack2f(float a, float b) {
    return pack2(__float2bfloat16_rn(a), __float2bfloat16_rn(b));
}
__device__ __forceinline__ float bflo(uint32_t u) {
    return __bfloat162float(__ushort_as_bfloat16((unsigned short)(u & 0xFFFF)));
}
__device__ __forceinline__ float bfhi(uint32_t u) {
    return __bfloat162float(__ushort_as_bfloat16((unsigned short)(u >> 16)));
}

// ---------------------------------------------------------------------------
// K1 (mma): blocks [0,2048): per (b, 2h): P1[32,(ky,p) x 64 c] = F2 @ x
//           blocks [2048,2056): generate G2 / Hinv / T / Bk tables
// ---------------------------------------------------------------------------
#define K1_SA 136
#define K1_SX 72
#define K1_SMEM_A 0
#define K1_SMEM_X (32 * K1_SA * 2)                       // 8704
#define K1_SMEM_TOTAL (K1_SMEM_X + 2 * 128 * K1_SX * 2)  // 45568

__global__ __launch_bounds__(256) void k1_mma(const float* __restrict__ x,
                                              const float* __restrict__ dk)
{
    extern __shared__ char sm[];
    const int t = threadIdx.x;

    if (blockIdx.x >= 2048) {
        // ---- table generation ----
        const int gid = (blockIdx.x - 2048) * 256 + t;
        const int gs  = 8 * 256;
        for (int i = gid; i < 64 * 256; i += gs) {           // G2
            int m = i >> 8, k = i & 255;
            int kxi = m >> 1, p = m & 1;
            int h = k >> 1, q = k & 1;
            int kx = (kxi < 16) ? kxi : (96 + kxi);
            float s, c;
            sincospif((float)(kx * h) * (1.0f / 64.0f), &s, &c);
            float v = (p == 0) ? (q == 0 ? c : s) : (q == 0 ? -s : c);
            g_G2[i] = __float2bfloat16_rn(v);
        }
        for (int i = gid; i < 256 * 64; i += gs) {           // Hinv
            int m = i >> 6, kq = i & 63;
            int h = m >> 1, p = m & 1;
            int kxi = kq >> 1, q = kq & 1;
            int kx = (kxi < 16) ? kxi : (96 + kxi);
            float s, c;
            sincospif((float)(kx * h) * (1.0f / 64.0f), &s, &c);
            float v = (p == 0) ? (q == 0 ? c : -s) : (q == 0 ? s : c);
            g_Hinv[i] = __float2bfloat16_rn(v * (1.0f / 128.0f));
        }
        for (int i = gid; i < WW * 32; i += gs) {            // T
            int w = i >> 5, j = i & 31, ky = j & 15;
            float s, c;
            sincospif((float)(ky * w) * (1.0f / 64.0f), &s, &c);
            float sc = (ky == 0) ? (1.0f / 128.0f) : (2.0f / 128.0f);
            g_T[i] = __float2bfloat16_rn((j < 16) ? c * sc : -s * sc);
        }
        for (int i = gid; i < CC * 128; i += gs) {           // Bk
            int c = i >> 7, k = i & 127;
            int kk = k & 63;
            float v = dk[kk * 64 + c];
            __nv_bfloat16 hi = __float2bfloat16_rn(v);
            g_Bk[i] = (k < 64) ? hi : __float2bfloat16_rn(v - __bfloat162float(hi));
        }
        gdc_launch();
        return;
    }

    const uint32_t sbase = smem_u32(sm);
    const int b    = blockIdx.x >> 6;
    const int hg   = blockIdx.x & 63;
    const int warp = t >> 5;
    const int lane = t & 31;

    // F2 fill (inline sincos, hidden under x-load latency)
    {
        const int m = t >> 3;
        const int ky = m >> 1, p = m & 1;
        const int w0 = (t & 7) * 16;
        #pragma unroll
        for (int j = 0; j < 16; j += 2) {
            float s0, c0, s1, c1;
            sincospif((float)(ky * (w0 + j))     * (1.0f / 64.0f), &s0, &c0);
            sincospif((float)(ky * (w0 + j + 1)) * (1.0f / 64.0f), &s1, &c1);
            uint32_t v = (p == 0) ? pack2f(c0, c1) : pack2f(-s0, -s1);
            *(uint32_t*)(sm + K1_SMEM_A + (m * K1_SA + w0 + j) * 2) = v;
        }
    }
    {
        const float4* xin = (const float4*)(x + ((size_t)(b * HH + hg * 2)) * WW * CC);
        for (int i = t; i < 2 * 128 * 16; i += 256) {
            float4 v = xin[i];
            int hl = i >> 11, w = (i >> 4) & 127, c4 = i & 15;
            uint32_t u0 = pack2f(v.x, v.y);
            uint32_t u1 = pack2f(v.z, v.w);
            *(uint2*)(sm + K1_SMEM_X + ((hl * 128 + w) * K1_SX + c4 * 4) * 2) = make_uint2(u0, u1);
        }
    }
    __syncthreads();

    const int hl = warp >> 2, nq = warp & 3;
    const uint32_t Ab = sbase + K1_SMEM_A;
    const uint32_t Xb = sbase + K1_SMEM_X + hl * 128 * K1_SX * 2;

    float acc[2][2][4];
    #pragma unroll
    for (int mt = 0; mt < 2; mt++)
        #pragma unroll
        for (int nt = 0; nt < 2; nt++)
            #pragma unroll
            for (int q = 0; q < 4; q++) acc[mt][nt][q] = 0.f;

    const int arow = lane & 15;
    const int acol = (lane >> 4) * 8;
    const int brow = (lane & 7) + ((lane >> 3) & 1) * 8;
    const int bcol = (lane >> 4) * 8;

    #pragma unroll
    for (int ks = 0; ks < 8; ks++) {
        uint32_t a[2][4];
        #pragma unroll
        for (int mt = 0; mt < 2; mt++) {
            uint32_t addr = Ab + (uint32_t)((mt * 16 + arow) * K1_SA + ks * 16 + acol) * 2;
            LDSM4(a[mt][0], a[mt][1], a[mt][2], a[mt][3], addr);
        }
        uint32_t b0, b1, b2, b3;
        uint32_t addr = Xb + (uint32_t)((ks * 16 + brow) * K1_SX + nq * 16 + bcol) * 2;
        LDSM4T(b0, b1, b2, b3, addr);
        #pragma unroll
        for (int mt = 0; mt < 2; mt++) {
            MMA16816(acc[mt][0], a[mt][0], a[mt][1], a[mt][2], a[mt][3], b0, b1);
            MMA16816(acc[mt][1], a[mt][0], a[mt][1], a[mt][2], a[mt][3], b2, b3);
        }
    }

    __syncthreads();
    __nv_bfloat16* stg = (__nv_bfloat16*)(sm + K1_SMEM_X);
    #pragma unroll
    for (int mt = 0; mt < 2; mt++)
        #pragma unroll
        for (int nt = 0; nt < 2; nt++)
            #pragma unroll
            for (int half = 0; half < 2; half++) {
                int m = mt * 16 + (lane >> 2) + half * 8;
                int ky = m >> 1, p = m & 1;
                int c = nq * 16 + nt * 8 + 2 * (lane & 3);
                int sr = ky * 4 + hl * 2 + p;
                *(uint32_t*)(stg + sr * 72 + c) =
                    pack2f(acc[mt][nt][half * 2], acc[mt][nt][half * 2 + 1]);
            }
    __syncthreads();
    {
        int sr = t >> 2, seg = t & 3;
        int ky = sr >> 2, hl2 = (sr >> 1) & 1, p = sr & 1;
        size_t row = (((size_t)(b * 16 + ky)) * 256 + (hg * 2 + hl2) * 2 + p) * 64 + seg * 16;
        const uint4* src = (const uint4*)(stg + sr * 72 + seg * 16);
        uint4* dst = (uint4*)(g_P1b + row);
        dst[0] = src[0]; dst[1] = src[1];
    }
    gdc_launch();
}

// ---------------------------------------------------------------------------
// K2 (mma): per (b,ky,ch): X[64 m=(kxi,p), 32 c] = G2[64x256] @ P1b[256, c-half]
// ---------------------------------------------------------------------------
#define K2_SA 264
#define K2_SB 40
#define K2_SMEM_A 0
#define K2_SMEM_B (64 * K2_SA * 2)                       // 33792
#define K2_SMEM_TOTAL (K2_SMEM_B + 256 * K2_SB * 2)      // 54272

__global__ __launch_bounds__(256) void k2_mma()
{
    extern __shared__ char sm[];
    const uint32_t sbase = smem_u32(sm);
    const int bky = blockIdx.x >> 1;
    const int b   = bky >> 4;
    const int ky  = bky & 15;
    const int ch  = blockIdx.x & 1;     // c-half
    const int t    = threadIdx.x;
    const int warp = t >> 5;
    const int lane = t & 31;

    gdc_wait();
    {
        const uint4* src = (const uint4*)g_G2;
        #pragma unroll
        for (int i = t; i < 64 * 32; i += 256) {
            int m = i >> 5, c8 = i & 31;
            *(uint4*)(sm + K2_SMEM_A + (m * K2_SA + c8 * 8) * 2) = src[i];
        }
    }
    {
        const __nv_bfloat16* base = g_P1b + ((size_t)(b * 16 + ky)) * 256 * 64 + ch * 32;
        #pragma unroll
        for (int i = t; i < 256 * 4; i += 256) {
            int r = i >> 2, s4 = i & 3;
            *(uint4*)(sm + K2_SMEM_B + (r * K2_SB + s4 * 8) * 2) =
                *(const uint4*)(base + (size_t)r * 64 + s4 * 8);
        }
    }
    __syncthreads();

    const int mi = warp >> 1, nh = warp & 1;
    float acc[2][4];
    #pragma unroll
    for (int nt = 0; nt < 2; nt++)
        #pragma unroll
        for (int q = 0; q < 4; q++) acc[nt][q] = 0.f;

    const int arow = lane & 15;
    const int acol = (lane >> 4) * 8;
    const int brow = (lane & 7) + ((lane >> 3) & 1) * 8;
    const int bcol = (lane >> 4) * 8;

    #pragma unroll
    for (int ks = 0; ks < 16; ks++) {
        uint32_t a0, a1, a2, a3;
        uint32_t aaddr = sbase + K2_SMEM_A + (uint32_t)((mi * 16 + arow) * K2_SA + ks * 16 + acol) * 2;
        LDSM4(a0, a1, a2, a3, aaddr);
        uint32_t b0, b1, b2, b3;
        uint32_t baddr = sbase + K2_SMEM_B
            + (uint32_t)((ks * 16 + brow) * K2_SB + nh * 16 + bcol) * 2;
        LDSM4T(b0, b1, b2, b3, baddr);
        MMA16816(acc[0], a0, a1, a2, a3, b0, b1);
        MMA16816(acc[1], a0, a1, a2, a3, b2, b3);
    }

    __syncthreads();
    __nv_bfloat16* stg = (__nv_bfloat16*)sm;   // [64 m][40]
    #pragma unroll
    for (int nt = 0; nt < 2; nt++)
        #pragma unroll
        for (int half = 0; half < 2; half++) {
            int m = mi * 16 + (lane >> 2) + half * 8;
            int c = nh * 16 + nt * 8 + 2 * (lane & 3);
            *(uint32_t*)(stg + m * 40 + c) = pack2f(acc[nt][half * 2], acc[nt][half * 2 + 1]);
        }
    __syncthreads();
    {
        int kxi = t >> 3, seg = t & 7;
        uint32_t vals[4];
        #pragma unroll
        for (int u = 0; u < 4; u++) {
            int cl = seg * 4 + u;
            vals[u] = pack2(stg[(2 * kxi) * 40 + cl], stg[(2 * kxi + 1) * 40 + cl]);
        }
        uint4* dst = (uint4*)(g_X2 + ((size_t)(kxi * 16 + ky) * 32 + b) * 128 + ch * 64 + seg * 8);
        dst[0] = make_uint4(vals[0], vals[1], vals[2], vals[3]);
    }
    gdc_launch();
}

// ---------------------------------------------------------------------------
// K3 (mma): per (kxi,ky,oh): Y[32 b, 64 (o-half,p)] = X2[32x128] @ W2[128 x half]
// ---------------------------------------------------------------------------
__global__ __launch_bounds__(256) void k3_mma(const float* __restrict__ w1r,
                                              const float* __restrict__ w1i,
                                              const float* __restrict__ w2r,
                                              const float* __restrict__ w2i)
{
    __shared__ __nv_bfloat16 sA[32 * 136];
    __shared__ __nv_bfloat16 sB[128 * 72];
    const int kq   = blockIdx.x >> 1;
    const int oh   = blockIdx.x & 1;
    const int o0   = oh * 32;
    const int kxi  = kq >> 4, ky = kq & 15;
    const int t    = threadIdx.x;
    const int warp = t >> 5;
    const int lane = t & 31;

    {
        const float* wr;
        const float* wi;
        if (kxi < 16) { size_t off = (size_t)(kxi * 16 + ky) * 4096; wr = w1r + off; wi = w1i + off; }
        else          { size_t off = (size_t)((kxi - 16) * 16 + ky) * 4096; wr = w2r + off; wi = w2i + off; }
        const int ii   = t >> 2;
        const int part = t & 3;
        const float4* wr4 = (const float4*)(wr + ii * 64 + o0 + part * 8);
        const float4* wi4 = (const float4*)(wi + ii * 64 + o0 + part * 8);
        float4 r0 = wr4[0], r1 = wr4[1];
        float4 i0 = wi4[0], i1 = wi4[1];
        uint4 q0a = make_uint4(pack2f(r0.x, i0.x), pack2f(r0.y, i0.y),
                               pack2f(r0.z, i0.z), pack2f(r0.w, i0.w));
        uint4 q0b = make_uint4(pack2f(r1.x, i1.x), pack2f(r1.y, i1.y),
                               pack2f(r1.z, i1.z), pack2f(r1.w, i1.w));
        uint4 q1a = make_uint4(pack2f(-i0.x, r0.x), pack2f(-i0.y, r0.y),
                               pack2f(-i0.z, r0.z), pack2f(-i0.w, r0.w));
        uint4 q1b = make_uint4(pack2f(-i1.x, r1.x), pack2f(-i1.y, r1.y),
                               pack2f(-i1.z, r1.z), pack2f(-i1.w, r1.w));
        *(uint4*)(sB + (2 * ii) * 72 + part * 16)       = q0a;
        *(uint4*)(sB + (2 * ii) * 72 + part * 16 + 8)   = q0b;
        *(uint4*)(sB + (2 * ii + 1) * 72 + part * 16)     = q1a;
        *(uint4*)(sB + (2 * ii + 1) * 72 + part * 16 + 8) = q1b;
    }
    gdc_wait();
    {
        const uint4* src = (const uint4*)(g_X2 + (size_t)kq * 32 * 128);
        #pragma unroll
        for (int i = t; i < 512; i += 256) {
            int r = i >> 4, c8 = i & 15;
            *(uint4*)(sA + r * 136 + c8 * 8) = src[i];
        }
    }
    __syncthreads();

    const uint32_t sAb = smem_u32(sA);
    const uint32_t sBb = smem_u32(sB);
    const int wm = warp >> 2, wn = warp & 3;
    float acc[2][4];
    #pragma unroll
    for (int nt = 0; nt < 2; nt++)
        #pragma unroll
        for (int q = 0; q < 4; q++) acc[nt][q] = 0.f;

    const int arow = lane & 15;
    const int acol = (lane >> 4) * 8;
    const int bkr  = (lane & 7) + ((lane >> 3) & 1) * 8;
    const int bcol = (lane >> 4) * 8;

    #pragma unroll
    for (int ks = 0; ks < 8; ks++) {
        uint32_t a0, a1, a2, a3;
        LDSM4(a0, a1, a2, a3,
              sAb + (uint32_t)((wm * 16 + arow) * 136 + ks * 16 + acol) * 2);
        uint32_t b0, b1, b2, b3;
        LDSM4T(b0, b1, b2, b3,
               sBb + (uint32_t)((ks * 16 + bkr) * 72 + wn * 16 + bcol) * 2);
        MMA16816(acc[0], a0, a1, a2, a3, b0, b1);
        MMA16816(acc[1], a0, a1, a2, a3, b2, b3);
    }

    __syncthreads();
    __nv_bfloat16* stg = sB;
    #pragma unroll
    for (int nt = 0; nt < 2; nt++)
        #pragma unroll
        for (int half = 0; half < 2; half++) {
            int bi = wm * 16 + (lane >> 2) + half * 8;
            int nl = wn * 16 + nt * 8 + 2 * (lane & 3);
            int ol = nl >> 1;
            stg[bi * 72 + ol]      = __float2bfloat16_rn(acc[nt][half * 2]);
            stg[bi * 72 + 32 + ol] = __float2bfloat16_rn(acc[nt][half * 2 + 1]);
        }
    __syncthreads();
    {
        int bi = t >> 3, seg = t & 7;
        int p = seg >> 2, qq = seg & 3;
        const uint4* src = (const uint4*)(stg + bi * 72 + p * 32 + qq * 8);
        uint4* dst = (uint4*)(g_Y2 + (((size_t)(bi * 16 + ky)) * 64 + kxi * 2 + p) * 64 + o0 + qq * 8);
        dst[0] = src[0];
    }
    gdc_launch();
}

// ---------------------------------------------------------------------------
// K4 (mma): per (b,ky): Z[256 (h,p), 64 c] = Hinv[256x64] @ Y2[64x64]
// ---------------------------------------------------------------------------
__global__ __launch_bounds__(256) void k4_mma()
{
    __shared__ __nv_bfloat16 sA[256 * 72];
    __shared__ __nv_bfloat16 sB[64 * 72];
    const int b    = blockIdx.x >> 4;
    const int ky   = blockIdx.x & 15;
    const int t    = threadIdx.x;
    const int warp = t >> 5;
    const int lane = t & 31;

    {
        const uint4* src = (const uint4*)g_Hinv;
        #pragma unroll
        for (int i = t; i < 256 * 8; i += 256) {
            int r = i >> 3, c8 = i & 7;
            *(uint4*)(sA + r * 72 + c8 * 8) = src[i];
        }
    }
    gdc_wait();
    {
        const uint4* src = (const uint4*)(g_Y2 + ((size_t)b * 16 + ky) * 64 * 64);
        #pragma unroll
        for (int i = t; i < 64 * 8; i += 256) {
            int r = i >> 3, c8 = i & 7;
            *(uint4*)(sB + r * 72 + c8 * 8) = src[i];
        }
    }
    __syncthreads();

    const uint32_t sAb = smem_u32(sA);
    const uint32_t sBb = smem_u32(sB);
    const int wm = warp >> 1, wn = warp & 1;

    float acc[4][4][4];
    #pragma unroll
    for (int mt = 0; mt < 4; mt++)
        #pragma unroll
        for (int g = 0; g < 4; g++)
            #pragma unroll
            for (int q = 0; q < 4; q++) acc[mt][g][q] = 0.f;

    const int arow = lane & 15;
    const int acol = (lane >> 4) * 8;
    const int bkr  = (lane & 7) + ((lane >> 3) & 1) * 8;
    const int bcol = (lane >> 4) * 8;

    #pragma unroll
    for (int ks = 0; ks < 4; ks++) {
        uint32_t a[4][4];
        #pragma unroll
        for (int mt = 0; mt < 4; mt++)
            LDSM4(a[mt][0], a[mt][1], a[mt][2], a[mt][3],
                  sAb + (uint32_t)((wm * 64 + mt * 16 + arow) * 72 + ks * 16 + acol) * 2);
        #pragma unroll
        for (int np = 0; np < 2; np++) {
            uint32_t b0, b1, b2, b3;
            LDSM4T(b0, b1, b2, b3,
                   sBb + (uint32_t)((ks * 16 + bkr) * 72 + wn * 32 + np * 16 + bcol) * 2);
            #pragma unroll
            for (int mt = 0; mt < 4; mt++) {
                MMA16816(acc[mt][np * 2],     a[mt][0], a[mt][1], a[mt][2], a[mt][3], b0, b1);
                MMA16816(acc[mt][np * 2 + 1], a[mt][0], a[mt][1], a[mt][2], a[mt][3], b2, b3);
            }
        }
    }

    #pragma unroll
    for (int mt = 0; mt < 4; mt++)
        #pragma unroll
        for (int g = 0; g < 4; g++)
            #pragma unroll
            for (int half = 0; half < 2; half++) {
                int m = wm * 64 + mt * 16 + (lane >> 2) + half * 8;
                int h = m >> 1, p = m & 1;
                int n = wn * 32 + g * 8 + 2 * (lane & 3);
                size_t addr = (((size_t)b * 32 + p * 16 + ky) * 128 + h) * 64 + n;
                *(uint32_t*)(g_Z2 + addr) = pack2f(acc[mt][g][half * 2], acc[mt][g][half * 2 + 1]);
            }
    gdc_launch();
}

// ---------------------------------------------------------------------------
// K5: mma.sync bf16 GEMM; 2 CTAs per (b,h), 64 w-rows each
// ---------------------------------------------------------------------------
#define SA 168
#define SB 136
#define SZ 72
#define K5_BIAS 0
#define K5_A    256
#define K5_B    (K5_A + 64 * SA * 2)      // 21760
#define K5_ZB   (K5_B + 64 * SB * 2)      // 39168
#define K5_SMEM (K5_ZB + 32 * SZ * 2)     // 43776

__global__ __launch_bounds__(256) void k5_mma(const float* __restrict__ x,
                                              const float* __restrict__ bias,
                                              float* __restrict__ out)
{
    extern __shared__ char smem[];
    const uint32_t sbase = smem_u32(smem);
    const int bh   = blockIdx.x >> 1;
    const int mh   = blockIdx.x & 1;
    const int t    = threadIdx.x;
    const int warp = t >> 5;
    const int lane = t & 31;

    // ---- A fill: x_hi (0..63), x_lo (64..127) ----
    {
        const int w  = t >> 2;
        const int c0 = (t & 3) * 16;
        const float4* xr4 = (const float4*)(x + (size_t)bh * 8192
                                            + (size_t)(mh * 64 + w) * 64 + c0);
        #pragma unroll
        for (int q = 0; q < 4; q++) {
            float4 v = xr4[q];
            __nv_bfloat16 h0 = __float2bfloat16_rn(v.x), h1 = __float2bfloat16_rn(v.y);
            __nv_bfloat16 h2 = __float2bfloat16_rn(v.z), h3 = __float2bfloat16_rn(v.w);
            uint32_t uhA = pack2(h0, h1), uhB = pack2(h2, h3);
            uint32_t ulA = pack2(__float2bfloat16_rn(v.x - __bfloat162float(h0)),
                                 __float2bfloat16_rn(v.y - __bfloat162float(h1)));
            uint32_t ulB = pack2(__float2bfloat16_rn(v.z - __bfloat162float(h2)),
                                 __float2bfloat16_rn(v.w - __bfloat162float(h3)));
            *(uint2*)(smem + K5_A + (w * SA + c0 + q * 4) * 2)      = make_uint2(uhA, uhB);
            *(uint2*)(smem + K5_A + (w * SA + 64 + c0 + q * 4) * 2) = make_uint2(ulA, ulB);
        }
    }
    // ---- A fill: T block (cols 128..159), table ----
    if (t < 64) {
        const uint4* ts = (const uint4*)(g_T + (mh * 64 + t) * 32);
        #pragma unroll
        for (int ch = 0; ch < 4; ch++)
            *(uint4*)(smem + K5_A + (t * SA + 128 + ch * 8) * 2) = ts[ch];
    }
    // ---- B fill: K_hi | K_lo table ----
    {
        const int c = t >> 2;
        const int q4 = t & 3;
        const uint4* src = (const uint4*)(g_Bk + c * 128 + q4 * 32);
        uint4* dst = (uint4*)(smem + K5_B + (c * SB + q4 * 32) * 2);
        dst[0] = src[0]; dst[1] = src[1]; dst[2] = src[2]; dst[3] = src[3];
    }
    if (t < 64) ((float*)(smem + K5_BIAS))[t] = bias[t];

    gdc_wait();
    // ---- Zb fill (depends on k4) ----
    {
        const int b = bh >> 7, h = bh & 127;
        const int j = t >> 3, seg = t & 7;
        const uint4* src = (const uint4*)(g_Z2 + (((size_t)b * 32 + j) * 128 + h) * 64 + seg * 8);
        *(uint4*)(smem + K5_ZB + (j * SZ + seg * 8) * 2) = src[0];
    }
    __syncthreads();

    const int wm = warp >> 1, wn = warp & 1;
    float acc[4][4];
    #pragma unroll
    for (int nt = 0; nt < 4; nt++) {
        acc[nt][0] = 0.f; acc[nt][1] = 0.f; acc[nt][2] = 0.f; acc[nt][3] = 0.f;
    }

    const int arow  = wm * 16 + (lane & 7) + ((lane >> 3) & 1) * 8;
    const int akoff = (lane >> 4) * 8;
    const int brow  = (lane & 7) + (lane >> 4) * 8;
    const int bkoff = ((lane >> 3) & 1) * 8;
    const int zrow  = (lane & 7) + ((lane >> 3) & 1) * 8;
    const int zcol  = (lane >> 4) * 8;

    const int passes[3][2] = { {0, 0}, {0, 64}, {64, 0} };
    #pragma unroll
    for (int p = 0; p < 3; p++) {
        const int kA = passes[p][0], kB = passes[p][1];
        #pragma unroll
        for (int ks = 0; ks < 4; ks++) {
            uint32_t a0, a1, a2, a3;
            uint32_t aaddr = sbase + K5_A + (uint32_t)(arow * SA + kA + ks * 16 + akoff) * 2;
            LDSM4(a0, a1, a2, a3, aaddr);
            #pragma unroll
            for (int nt2 = 0; nt2 < 2; nt2++) {
                uint32_t b0, b1, b2, b3;
                uint32_t baddr = sbase + K5_B
                    + (uint32_t)((wn * 32 + nt2 * 16 + brow) * SB + kB + ks * 16 + bkoff) * 2;
                LDSM4(b0, b1, b2, b3, baddr);
                MMA16816(acc[2 * nt2],     a0, a1, a2, a3, b0, b1);
                MMA16816(acc[2 * nt2 + 1], a0, a1, a2, a3, b2, b3);
            }
        }
    }
    #pragma unroll
    for (int ks = 0; ks < 2; ks++) {
        uint32_t a0, a1, a2, a3;
        uint32_t aaddr = sbase + K5_A + (uint32_t)(arow * SA + 128 + ks * 16 + akoff) * 2;
        LDSM4(a0, a1, a2, a3, aaddr);
        #pragma unroll
        for (int nt2 = 0; nt2 < 2; nt2++) {
            uint32_t b0, b1, b2, b3;
            uint32_t baddr = sbase + K5_ZB
                + (uint32_t)((ks * 16 + zrow) * SZ + wn * 32 + nt2 * 16 + zcol) * 2;
            LDSM4T(b0, b1, b2, b3, baddr);
            MMA16816(acc[2 * nt2],     a0, a1, a2, a3, b0, b1);
            MMA16816(acc[2 * nt2 + 1], a0, a1, a2, a3, b2, b3);
        }
    }

    const int r0 = wm * 16 + (lane >> 2);
    const float* bs = (const float*)(smem + K5_BIAS);
    #pragma unroll
    for (int half = 0; half < 2; half++) {
        const int r = r0 + half * 8;
        float* orow = out + (size_t)bh * 8192 + (size_t)(mh * 64 + r) * 64;
        #pragma unroll
        for (int nt = 0; nt < 4; nt++) {
            const int c = wn * 32 + nt * 8 + 2 * (lane & 3);
            uint32_t hp = *(const uint32_t*)(smem + K5_A + (r * SA + c) * 2);
            uint32_t lp = *(const uint32_t*)(smem + K5_A + (r * SA + 64 + c) * 2);
            float res0 = bflo(hp) + bflo(lp);
            float res1 = bfhi(hp) + bfhi(lp);
            float s0 = acc[nt][half * 2 + 0] + res0 + bs[c];
            float s1 = acc[nt][half * 2 + 1] + res1 + bs[c + 1];
            float u0 = 0.7978845608028654f * (s0 + 0.044715f * s0 * s0 * s0);
            float u1 = 0.7978845608028654f * (s1 + 0.044715f * s1 * s1 * s1);
            float g0 = 0.5f * s0 * (1.0f + tanh_approx(u0));
            float g1 = 0.5f * s1 * (1.0f + tanh_approx(u1));
            *(float2*)(orow + c) = make_float2(g0, g1);
        }
    }
}

// ---------------------------------------------------------------------------
// Launch (PDL-chained)
// ---------------------------------------------------------------------------
extern "C" void kernel_launch(void* const* d_in, const int* in_sizes, int n_in,
                              void* d_out, int out_size)
{
    const float* x   = (const float*)d_in[0];
    const float* w1r = (const float*)d_in[1];
    const float* w1i = (const float*)d_in[2];
    const float* w2r = (const float*)d_in[3];
    const float* w2i = (const float*)d_in[4];
    const float* dk  = (const float*)d_in[5];
    const float* db  = (const float*)d_in[6];
    float* out = (float*)d_out;

    static int configured = 0;
    if (!configured) {
        cudaFuncSetAttribute(k1_mma, cudaFuncAttributeMaxDynamicSharedMemorySize, K1_SMEM_TOTAL);
        cudaFuncSetAttribute(k2_mma, cudaFuncAttributeMaxDynamicSharedMemorySize, K2_SMEM_TOTAL);
        cudaFuncSetAttribute(k5_mma, cudaFuncAttributeMaxDynamicSharedMemorySize, K5_SMEM);
        configured = 1;
    }

    cudaLaunchAttribute at[1];
    at[0].id = cudaLaunchAttributeProgrammaticStreamSerialization;
    at[0].val.programmaticStreamSerializationAllowed = 1;

    k1_mma<<<BB * 64 + 8, 256, K1_SMEM_TOTAL>>>(x, dk);

    {
        cudaLaunchConfig_t cfg = {};
        cfg.gridDim = dim3(BB * MY * 2);
        cfg.blockDim = dim3(256);
        cfg.dynamicSmemBytes = K2_SMEM_TOTAL;
        cfg.stream = 0;
        cfg.attrs = at; cfg.numAttrs = 1;
        cudaLaunchKernelEx(&cfg, k2_mma);
    }
    {
        cudaLaunchConfig_t cfg = {};
        cfg.gridDim = dim3(1024);
        cfg.blockDim = dim3(256);
        cfg.dynamicSmemBytes = 0;
        cfg.stream = 0;
        cfg.attrs = at; cfg.numAttrs = 1;
        cudaLaunchKernelEx(&cfg, k3_mma, w1r, w1i, w2r, w2i);
    }
    {
        cudaLaunchConfig_t cfg = {};
        cfg.gridDim = dim3(BB * MY);
        cfg.blockDim = dim3(256);
        cfg.dynamicSmemBytes = 0;
        cfg.stream = 0;
        cfg.attrs = at; cfg.numAttrs = 1;
        cudaLaunchKernelEx(&cfg, k4_mma);
    }
    {
        cudaLaunchConfig_t cfg = {};
        cfg.gridDim = dim3(BB * HH * 2);
        cfg.blockDim = dim3(256);
        cfg.dynamicSmemBytes = K5_SMEM;
        cfg.stream = 0;
        cfg.attrs = at; cfg.numAttrs = 1;
        cudaLaunchKernelEx(&cfg, k5_mma, x, db, out);
    }
}